// round 10
// baseline (speedup 1.0000x reference)
#include <cuda_runtime.h>
#include <cuda_bf16.h>
#include <cstdint>

#define B_  4
#define T_  2048
#define D_  1024
#define H_  16
#define HD_ 64
#define M_  (B_*T_)
#define NQKV (3*D_)
#define GK   1024

// ---------------------------------------------------------------------------
// Scratch (allocation-free __device__ globals)
// ---------------------------------------------------------------------------
__device__ __nv_bfloat16 g_xhi[(size_t)M_*D_];
__device__ __nv_bfloat16 g_xlo[(size_t)M_*D_];
__device__ __nv_bfloat16 g_wqkv_hi[(size_t)NQKV*D_];   // transposed [N,K]
__device__ __nv_bfloat16 g_wqkv_lo[(size_t)NQKV*D_];
__device__ __nv_bfloat16 g_wp_hi[(size_t)D_*D_];       // transposed [N,K]
__device__ __nv_bfloat16 g_wp_lo[(size_t)D_*D_];
__device__ __nv_bfloat16 g_atthi[(size_t)M_*D_];
__device__ __nv_bfloat16 g_attlo[(size_t)M_*D_];

// split-bf16 Q/K/V in [B,H,T,Hd] layout (Q pre-scaled by 1/sqrt(Hd))
__device__ __nv_bfloat16 g_qhi[(size_t)B_*H_*T_*HD_];
__device__ __nv_bfloat16 g_qlo[(size_t)B_*H_*T_*HD_];
__device__ __nv_bfloat16 g_khi[(size_t)B_*H_*T_*HD_];
__device__ __nv_bfloat16 g_klo[(size_t)B_*H_*T_*HD_];
__device__ __nv_bfloat16 g_vhi[(size_t)B_*H_*T_*HD_];
__device__ __nv_bfloat16 g_vlo[(size_t)B_*H_*T_*HD_];

// ---------------------------------------------------------------------------
// Helpers (plain sm_80+ PTX; nothing arch-'a'-gated)
// ---------------------------------------------------------------------------
__device__ __forceinline__ uint32_t smem_u32_of(const void* p) {
    uint32_t a;
    asm("{ .reg .u64 t; cvta.to.shared.u64 t, %1; cvt.u32.u64 %0, t; }" : "=r"(a) : "l"(p));
    return a;
}

__device__ __forceinline__ void cp_async16(uint32_t saddr, const void* gptr) {
    asm volatile("cp.async.cg.shared.global [%0], [%1], 16;"
                 :: "r"(saddr), "l"(gptr) : "memory");
}

__device__ __forceinline__ void mma_bf16(float* c, const uint32_t* a, const uint32_t* b) {
    asm volatile(
        "mma.sync.aligned.m16n8k16.row.col.f32.bf16.bf16.f32 "
        "{%0,%1,%2,%3}, {%4,%5,%6,%7}, {%8,%9}, {%0,%1,%2,%3};"
        : "+f"(c[0]), "+f"(c[1]), "+f"(c[2]), "+f"(c[3])
        : "r"(a[0]), "r"(a[1]), "r"(a[2]), "r"(a[3]), "r"(b[0]), "r"(b[1]));
}

__device__ __forceinline__ void packsplit2(float x, float y, uint32_t& hi, uint32_t& lo) {
    __nv_bfloat162 h = __floats2bfloat162_rn(x, y);
    float rx = x - __bfloat162float(h.x);
    float ry = y - __bfloat162float(h.y);
    __nv_bfloat162 l = __floats2bfloat162_rn(rx, ry);
    hi = *(uint32_t*)&h;
    lo = *(uint32_t*)&l;
}

// ---------------------------------------------------------------------------
// Split fp32 -> (hi, lo) bf16, elementwise
// ---------------------------------------------------------------------------
__global__ __launch_bounds__(256) void split_kernel(
    const float* __restrict__ in, __nv_bfloat16* __restrict__ hi,
    __nv_bfloat16* __restrict__ lo, int n4)
{
    int i = blockIdx.x * blockDim.x + threadIdx.x;
    if (i >= n4) return;
    float4 v = ((const float4*)in)[i];
    __nv_bfloat16 h0 = __float2bfloat16(v.x), h1 = __float2bfloat16(v.y);
    __nv_bfloat16 h2 = __float2bfloat16(v.z), h3 = __float2bfloat16(v.w);
    __nv_bfloat16 l0 = __float2bfloat16(v.x - __bfloat162float(h0));
    __nv_bfloat16 l1 = __float2bfloat16(v.y - __bfloat162float(h1));
    __nv_bfloat16 l2 = __float2bfloat16(v.z - __bfloat162float(h2));
    __nv_bfloat16 l3 = __float2bfloat16(v.w - __bfloat162float(h3));
    ((__nv_bfloat162*)hi)[i*2+0] = __nv_bfloat162(h0, h1);
    ((__nv_bfloat162*)hi)[i*2+1] = __nv_bfloat162(h2, h3);
    ((__nv_bfloat162*)lo)[i*2+0] = __nv_bfloat162(l0, l1);
    ((__nv_bfloat162*)lo)[i*2+1] = __nv_bfloat162(l2, l3);
}

// ---------------------------------------------------------------------------
// Transpose + split: W[K,N] fp32 -> Wt_hi/lo[N,K] bf16
// ---------------------------------------------------------------------------
__global__ __launch_bounds__(256) void transpose_split_kernel(
    const float* __restrict__ W, __nv_bfloat16* __restrict__ hi,
    __nv_bfloat16* __restrict__ lo, int K, int N)
{
    __shared__ float tile[32][33];
    const int tx = threadIdx.x, ty = threadIdx.y;
    const int n0 = blockIdx.x * 32, k0 = blockIdx.y * 32;
#pragma unroll
    for (int i = 0; i < 32; i += 8)
        tile[ty + i][tx] = W[(size_t)(k0 + ty + i) * N + n0 + tx];
    __syncthreads();
#pragma unroll
    for (int i = 0; i < 32; i += 8) {
        float v = tile[tx][ty + i];
        __nv_bfloat16 h = __float2bfloat16(v);
        __nv_bfloat16 l = __float2bfloat16(v - __bfloat162float(h));
        size_t o = (size_t)(n0 + ty + i) * K + (k0 + tx);
        hi[o] = h; lo[o] = l;
    }
}

// ---------------------------------------------------------------------------
// HMMA split-bf16 GEMM. Tile 128x128, 8 warps (2m x 4n), K-chunk 16,
// 3-stage cp.async ring, 2 CTAs/SM.
// Smem row: 16 bf16 data + 8 pad = 48 B = 12 words (frag loads conflict-free).
// qkv_mode epilogue writes bf16 hi/lo Q(scaled)/K/V; else fp32 outp.
// ---------------------------------------------------------------------------
#define BKC      16
#define NCHUNK   (GK/BKC)            // 64
#define ROW_W    12                  // words per padded smem row (48 B)
#define OPB      (128*48)            // 6144 B per operand per stage
#define STAGE_B  (4*OPB)             // 24576
#define NSTAGE   3
#define GEMM_SMEM (NSTAGE*STAGE_B)   // 73728

__global__ __launch_bounds__(256, 2) void hmma_gemm_kernel(
    const __nv_bfloat16* __restrict__ Ahi, const __nv_bfloat16* __restrict__ Alo,
    const __nv_bfloat16* __restrict__ Bhi, const __nv_bfloat16* __restrict__ Blo,
    const float* __restrict__ bias, float* __restrict__ outp, int qkv_mode)
{
    extern __shared__ char smem[];
    const int tid  = threadIdx.x;
    const int lane = tid & 31;
    const int wid  = tid >> 5;
    const int warp_m = wid & 1;
    const int warp_n = wid >> 1;
    const int n0 = blockIdx.x << 7;
    const int m0 = blockIdx.y << 7;
    const int r4 = lane >> 2, c4 = lane & 3;

    const __nv_bfloat16* gops[4] = {
        Ahi + (size_t)m0 * GK, Alo + (size_t)m0 * GK,
        Bhi + (size_t)n0 * GK, Blo + (size_t)n0 * GK };

    const int lrow = tid >> 1;       // 0..127
    const int lq   = tid & 1;        // 0..1  (16B chunk within 32B row)

    auto stage_load = [&](int c, int s) {
#pragma unroll
        for (int op = 0; op < 4; op++) {
            char* sd = smem + s * STAGE_B + op * OPB;
            uint32_t da = smem_u32_of(sd + lrow * 48 + lq * 16);
            cp_async16(da, (const char*)(gops[op] + (size_t)lrow * GK + c * BKC) + lq * 16);
        }
    };

    float acc[4][4][4];
#pragma unroll
    for (int i = 0; i < 4; i++)
#pragma unroll
        for (int j = 0; j < 4; j++)
#pragma unroll
            for (int r = 0; r < 4; r++) acc[i][j][r] = 0.0f;

    stage_load(0, 0);
    asm volatile("cp.async.commit_group;" ::: "memory");
    stage_load(1, 1);
    asm volatile("cp.async.commit_group;" ::: "memory");

    for (int c = 0; c < NCHUNK; c++) {
        // wait for group c to complete
        if (c + 2 < NCHUNK)      asm volatile("cp.async.wait_group 1;" ::: "memory");
        else if (c + 2 == NCHUNK) asm volatile("cp.async.wait_group 1;" ::: "memory");
        else if (c + 1 == NCHUNK - 0 - 1) asm volatile("cp.async.wait_group 0;" ::: "memory");
        else                      asm volatile("cp.async.wait_group 0;" ::: "memory");
        __syncthreads();

        if (c + 2 < NCHUNK) {
            stage_load(c + 2, (c + 2) % NSTAGE);
            asm volatile("cp.async.commit_group;" ::: "memory");
        }

        const uint32_t* sAh = (const uint32_t*)(smem + (c % NSTAGE) * STAGE_B);
        const uint32_t* sAl = sAh + OPB / 4;
        const uint32_t* sBh = sAl + OPB / 4;
        const uint32_t* sBl = sBh + OPB / 4;

        const int ar = warp_m * 64 + r4;
        uint32_t ah[4][4], al[4][4], bh[4][2], bl[4][2];
#pragma unroll
        for (int wm = 0; wm < 4; wm++) {
            int r0 = (ar + wm * 16) * ROW_W;
            int r8 = (ar + wm * 16 + 8) * ROW_W;
            ah[wm][0] = sAh[r0 + c4];   ah[wm][1] = sAh[r8 + c4];
            ah[wm][2] = sAh[r0 + c4+4]; ah[wm][3] = sAh[r8 + c4+4];
            al[wm][0] = sAl[r0 + c4];   al[wm][1] = sAl[r8 + c4];
            al[wm][2] = sAl[r0 + c4+4]; al[wm][3] = sAl[r8 + c4+4];
        }
#pragma unroll
        for (int wn = 0; wn < 4; wn++) {
            int br = (warp_n * 32 + wn * 8 + r4) * ROW_W;
            bh[wn][0] = sBh[br + c4]; bh[wn][1] = sBh[br + c4 + 4];
            bl[wn][0] = sBl[br + c4]; bl[wn][1] = sBl[br + c4 + 4];
        }
#pragma unroll
        for (int wm = 0; wm < 4; wm++)
#pragma unroll
            for (int wn = 0; wn < 4; wn++) {
                mma_bf16(acc[wm][wn], ah[wm], bh[wn]);
                mma_bf16(acc[wm][wn], ah[wm], bl[wn]);
                mma_bf16(acc[wm][wn], al[wm], bh[wn]);
            }
    }

    // ---- Epilogue ----
#pragma unroll
    for (int wm = 0; wm < 4; wm++) {
#pragma unroll
        for (int wn = 0; wn < 4; wn++) {
            int col = n0 + warp_n * 32 + wn * 8 + (c4 << 1);
            float b0 = __ldg(bias + col), b1 = __ldg(bias + col + 1);
#pragma unroll
            for (int h8 = 0; h8 < 2; h8++) {
                int row = m0 + warp_m * 64 + wm * 16 + r4 + h8 * 8;
                float v0 = acc[wm][wn][h8*2+0] + b0;
                float v1 = acc[wm][wn][h8*2+1] + b1;
                if (qkv_mode) {
                    int three = col >> 10;
                    int h     = (col & 1023) >> 6;
                    int dcol  = col & 63;
                    if (three == 0) { v0 *= 0.125f; v1 *= 0.125f; }   // fold 1/sqrt(64)
                    __nv_bfloat16* dh = (three == 0) ? g_qhi : (three == 1) ? g_khi : g_vhi;
                    __nv_bfloat16* dl = (three == 0) ? g_qlo : (three == 1) ? g_klo : g_vlo;
                    uint32_t phv, plv;
                    packsplit2(v0, v1, phv, plv);
                    int b = row >> 11, t = row & 2047;
                    size_t o = ((size_t)(b*H_ + h)*T_ + t) * HD_ + dcol;
                    *(uint32_t*)(dh + o) = phv;
                    *(uint32_t*)(dl + o) = plv;
                } else {
                    float2 o2; o2.x = v0; o2.y = v1;
                    *(float2*)(outp + (size_t)row * D_ + col) = o2;
                }
            }
        }
    }
}

// ---------------------------------------------------------------------------
// HMMA flash attention (verified Round 9 structure). Epilogue now emits
// split-bf16 directly to g_atthi/g_attlo (no fp32 round trip).
// Heavy (large-qb) blocks scheduled first.
// ---------------------------------------------------------------------------
#define KSTR 72          // padded smem row: 72 bf16 = 36 words (conflict-free)

__global__ __launch_bounds__(256) void attn_mma_kernel()
{
    __shared__ __nv_bfloat16 sK[2][64*KSTR];    // [hi/lo][token][dim]
    __shared__ __nv_bfloat16 sVt[2][64*KSTR];   // [hi/lo][dim][token]

    const int tid = threadIdx.x, lane = tid & 31, wid = tid >> 5;
    const int qb = gridDim.x - 1 - blockIdx.x;   // heavy blocks first
    const int bh = blockIdx.y;
    const int m0 = qb << 7;
    const int r4 = lane >> 2, c4 = lane & 3;
    const int rowblk = wid * 16 + r4;

    const size_t bho = (size_t)bh * T_ * HD_;
    const __nv_bfloat16* Kh = g_khi + bho;
    const __nv_bfloat16* Kl = g_klo + bho;
    const __nv_bfloat16* Vh = g_vhi + bho;
    const __nv_bfloat16* Vl = g_vlo + bho;

    // ---- Q fragments (pre-scaled), registers for whole sweep ----
    uint32_t qa[2][4][4];
    {
        const __nv_bfloat16* srcs[2] = { g_qhi + bho, g_qlo + bho };
#pragma unroll
        for (int hl = 0; hl < 2; hl++) {
            const __nv_bfloat16* S = srcs[hl];
            const size_t r0 = (size_t)(m0 + rowblk) * HD_;
            const size_t r8 = r0 + 8 * HD_;
#pragma unroll
            for (int ks = 0; ks < 4; ks++) {
                int col0 = ks * 16 + 2 * c4;
                qa[hl][ks][0] = *(const uint32_t*)(S + r0 + col0);
                qa[hl][ks][1] = *(const uint32_t*)(S + r8 + col0);
                qa[hl][ks][2] = *(const uint32_t*)(S + r0 + col0 + 8);
                qa[hl][ks][3] = *(const uint32_t*)(S + r8 + col0 + 8);
            }
        }
    }

    float m_i[2] = { -1e30f, -1e30f };
    float l_i[2] = { 0.0f, 0.0f };
    float o[8][4];
#pragma unroll
    for (int j = 0; j < 8; j++)
#pragma unroll
        for (int r = 0; r < 4; r++) o[j][r] = 0.0f;

    const int ktmax = 2 * qb + 1;
    for (int kt = 0; kt <= ktmax; kt++) {
        if (kt) __syncthreads();

#pragma unroll
        for (int hl = 0; hl < 2; hl++) {
            const __nv_bfloat16* src = hl ? Kl : Kh;
#pragma unroll
            for (int rep = 0; rep < 2; rep++) {
                int idx = tid + (rep << 8);
                int row = idx >> 3, ch = idx & 7;
                uint32_t da = smem_u32_of(&sK[hl][row * KSTR]) + ch * 16;
                cp_async16(da, (const char*)(src + (size_t)(kt*64 + row) * HD_) + ch * 16);
            }
        }
        asm volatile("cp.async.commit_group;" ::: "memory");

#pragma unroll
        for (int hl = 0; hl < 2; hl++) {
            const __nv_bfloat16* src = hl ? Vl : Vh;
#pragma unroll
            for (int rep = 0; rep < 4; rep++) {
                int idx = tid + (rep << 8);
                int t = idx >> 4, dg = (idx & 15) << 2;
                uint2 v = *(const uint2*)(src + (size_t)(kt*64 + t) * HD_ + dg);
                __nv_bfloat162 p0 = *(__nv_bfloat162*)&v.x;
                __nv_bfloat162 p1 = *(__nv_bfloat162*)&v.y;
                sVt[hl][(dg+0)*KSTR + t] = p0.x;
                sVt[hl][(dg+1)*KSTR + t] = p0.y;
                sVt[hl][(dg+2)*KSTR + t] = p1.x;
                sVt[hl][(dg+3)*KSTR + t] = p1.y;
            }
        }
        asm volatile("cp.async.wait_group 0;" ::: "memory");
        __syncthreads();

        const bool active = !(kt == ktmax && wid < 4);
        if (active) {
            float s[8][4];
#pragma unroll
            for (int j = 0; j < 8; j++)
#pragma unroll
                for (int r = 0; r < 4; r++) s[j][r] = 0.0f;

            const uint32_t* wKh = (const uint32_t*)sK[0];
            const uint32_t* wKl = (const uint32_t*)sK[1];
#pragma unroll
            for (int ks = 0; ks < 4; ks++) {
                const int w0 = ks * 8 + c4;
#pragma unroll
                for (int j = 0; j < 8; j++) {
                    int br = (j * 8 + r4) * 36;
                    uint32_t kb[2] = { wKh[br + w0], wKh[br + w0 + 4] };
                    uint32_t kl2[2] = { wKl[br + w0], wKl[br + w0 + 4] };
                    mma_bf16(s[j], qa[0][ks], kb);
                    mma_bf16(s[j], qa[0][ks], kl2);
                    mma_bf16(s[j], qa[1][ks], kb);
                }
            }

            if (kt >= 2 * qb) {
                int kbase = (kt - 2 * qb) << 6;
#pragma unroll
                for (int j = 0; j < 8; j++) {
                    int col = kbase + j * 8 + 2 * c4;
                    if (col     > rowblk)     s[j][0] = -1e30f;
                    if (col + 1 > rowblk)     s[j][1] = -1e30f;
                    if (col     > rowblk + 8) s[j][2] = -1e30f;
                    if (col + 1 > rowblk + 8) s[j][3] = -1e30f;
                }
            }

            float mx0 = -1e30f, mx1 = -1e30f;
#pragma unroll
            for (int j = 0; j < 8; j++) {
                mx0 = fmaxf(mx0, fmaxf(s[j][0], s[j][1]));
                mx1 = fmaxf(mx1, fmaxf(s[j][2], s[j][3]));
            }
            mx0 = fmaxf(mx0, __shfl_xor_sync(0xffffffffu, mx0, 1));
            mx0 = fmaxf(mx0, __shfl_xor_sync(0xffffffffu, mx0, 2));
            mx1 = fmaxf(mx1, __shfl_xor_sync(0xffffffffu, mx1, 1));
            mx1 = fmaxf(mx1, __shfl_xor_sync(0xffffffffu, mx1, 2));

            float mn0 = fmaxf(m_i[0], mx0), mn1 = fmaxf(m_i[1], mx1);
            float al0 = __expf(m_i[0] - mn0), al1 = __expf(m_i[1] - mn1);
            m_i[0] = mn0; m_i[1] = mn1;

            float rs0 = 0.0f, rs1 = 0.0f;
#pragma unroll
            for (int j = 0; j < 8; j++) {
                s[j][0] = __expf(s[j][0] - mn0);
                s[j][1] = __expf(s[j][1] - mn0);
                s[j][2] = __expf(s[j][2] - mn1);
                s[j][3] = __expf(s[j][3] - mn1);
                rs0 += s[j][0] + s[j][1];
                rs1 += s[j][2] + s[j][3];
            }
            rs0 += __shfl_xor_sync(0xffffffffu, rs0, 1);
            rs0 += __shfl_xor_sync(0xffffffffu, rs0, 2);
            rs1 += __shfl_xor_sync(0xffffffffu, rs1, 1);
            rs1 += __shfl_xor_sync(0xffffffffu, rs1, 2);
            l_i[0] = l_i[0] * al0 + rs0;
            l_i[1] = l_i[1] * al1 + rs1;

#pragma unroll
            for (int j = 0; j < 8; j++) {
                o[j][0] *= al0; o[j][1] *= al0;
                o[j][2] *= al1; o[j][3] *= al1;
            }

            const uint32_t* wVh = (const uint32_t*)sVt[0];
            const uint32_t* wVl = (const uint32_t*)sVt[1];
#pragma unroll
            for (int ks = 0; ks < 4; ks++) {
                uint32_t pah[4], pal[4];
                packsplit2(s[2*ks  ][0], s[2*ks  ][1], pah[0], pal[0]);
                packsplit2(s[2*ks  ][2], s[2*ks  ][3], pah[1], pal[1]);
                packsplit2(s[2*ks+1][0], s[2*ks+1][1], pah[2], pal[2]);
                packsplit2(s[2*ks+1][2], s[2*ks+1][3], pah[3], pal[3]);
                const int w0 = ks * 8 + c4;
#pragma unroll
                for (int j = 0; j < 8; j++) {
                    int br = (j * 8 + r4) * 36;
                    uint32_t vb[2] = { wVh[br + w0], wVh[br + w0 + 4] };
                    uint32_t vl2[2] = { wVl[br + w0], wVl[br + w0 + 4] };
                    mma_bf16(o[j], pah, vb);
                    mma_bf16(o[j], pah, vl2);
                    mma_bf16(o[j], pal, vb);
                }
            }
        }
    }

    // ---- normalize, split, write bf16 hi/lo att output [B,T,D] ----
    float inv0 = 1.0f / l_i[0], inv1 = 1.0f / l_i[1];
    const int b = bh >> 4, h = bh & 15;
    const int t0 = m0 + rowblk, t1 = t0 + 8;
#pragma unroll
    for (int j = 0; j < 8; j++) {
        int dim = h * 64 + j * 8 + 2 * c4;
        uint32_t h0, l0v, h1, l1v;
        packsplit2(o[j][0] * inv0, o[j][1] * inv0, h0, l0v);
        packsplit2(o[j][2] * inv1, o[j][3] * inv1, h1, l1v);
        size_t o0 = (size_t)(b*T_ + t0) * D_ + dim;
        size_t o1 = (size_t)(b*T_ + t1) * D_ + dim;
        *(uint32_t*)(g_atthi + o0) = h0;
        *(uint32_t*)(g_attlo + o0) = l0v;
        *(uint32_t*)(g_atthi + o1) = h1;
        *(uint32_t*)(g_attlo + o1) = l1v;
    }
}

// ---------------------------------------------------------------------------
extern "C" void kernel_launch(void* const* d_in, const int* in_sizes, int n_in,
                              void* d_out, int out_size)
{
    const float* x      = (const float*)d_in[0];
    const float* w_qkv  = (const float*)d_in[1];
    const float* b_qkv  = (const float*)d_in[2];
    const float* w_proj = (const float*)d_in[3];
    const float* b_proj = (const float*)d_in[4];
    float* out = (float*)d_out;

    __nv_bfloat16 *xhi, *xlo, *wqh, *wql, *wph, *wpl, *ahi, *alo;
    cudaGetSymbolAddress((void**)&xhi, g_xhi);
    cudaGetSymbolAddress((void**)&xlo, g_xlo);
    cudaGetSymbolAddress((void**)&wqh, g_wqkv_hi);
    cudaGetSymbolAddress((void**)&wql, g_wqkv_lo);
    cudaGetSymbolAddress((void**)&wph, g_wp_hi);
    cudaGetSymbolAddress((void**)&wpl, g_wp_lo);
    cudaGetSymbolAddress((void**)&ahi, g_atthi);
    cudaGetSymbolAddress((void**)&alo, g_attlo);

    cudaFuncSetAttribute(hmma_gemm_kernel,
                         cudaFuncAttributeMaxDynamicSharedMemorySize, GEMM_SMEM);

    // 1) split X, transpose+split weights
    split_kernel<<<(M_*D_/4 + 255)/256, 256>>>(x, xhi, xlo, M_*D_/4);
    transpose_split_kernel<<<dim3(NQKV/32, D_/32), dim3(32, 8)>>>(w_qkv, wqh, wql, D_, NQKV);
    transpose_split_kernel<<<dim3(D_/32,  D_/32), dim3(32, 8)>>>(w_proj, wph, wpl, D_, D_);

    // 2) QKV HMMA GEMM -> split-bf16 q/k/v (q pre-scaled)
    hmma_gemm_kernel<<<dim3(NQKV/128, M_/128), 256, GEMM_SMEM>>>(
        xhi, xlo, wqh, wql, b_qkv, nullptr, 1);

    // 3) HMMA flash attention -> split-bf16 att output (fused split epilogue)
    attn_mma_kernel<<<dim3(T_/128, B_*H_), 256>>>();

    // 4) proj HMMA GEMM -> out
    hmma_gemm_kernel<<<dim3(D_/128, M_/128), 256, GEMM_SMEM>>>(
        ahi, alo, wph, wpl, b_proj, out, 0);
}

// round 11
// speedup vs baseline: 1.0473x; 1.0473x over previous
#include <cuda_runtime.h>
#include <cuda_bf16.h>
#include <cstdint>

#define B_  4
#define T_  2048
#define D_  1024
#define H_  16
#define HD_ 64
#define M_  (B_*T_)
#define NQKV (3*D_)
#define GK   1024

// ---------------------------------------------------------------------------
// Scratch (allocation-free __device__ globals)
// ---------------------------------------------------------------------------
__device__ __nv_bfloat16 g_xhi[(size_t)M_*D_];
__device__ __nv_bfloat16 g_xlo[(size_t)M_*D_];
__device__ __nv_bfloat16 g_wqkv_hi[(size_t)NQKV*D_];   // transposed [N,K]
__device__ __nv_bfloat16 g_wqkv_lo[(size_t)NQKV*D_];
__device__ __nv_bfloat16 g_wp_hi[(size_t)D_*D_];       // transposed [N,K]
__device__ __nv_bfloat16 g_wp_lo[(size_t)D_*D_];
__device__ __nv_bfloat16 g_atthi[(size_t)M_*D_];
__device__ __nv_bfloat16 g_attlo[(size_t)M_*D_];

// split-bf16 Q/K/V in [B,H,T,Hd] layout (Q pre-scaled by 1/sqrt(Hd))
__device__ __nv_bfloat16 g_qhi[(size_t)B_*H_*T_*HD_];
__device__ __nv_bfloat16 g_qlo[(size_t)B_*H_*T_*HD_];
__device__ __nv_bfloat16 g_khi[(size_t)B_*H_*T_*HD_];
__device__ __nv_bfloat16 g_klo[(size_t)B_*H_*T_*HD_];
__device__ __nv_bfloat16 g_vhi[(size_t)B_*H_*T_*HD_];
__device__ __nv_bfloat16 g_vlo[(size_t)B_*H_*T_*HD_];

// ---------------------------------------------------------------------------
// Helpers (plain sm_80+ PTX; nothing arch-'a'-gated)
// ---------------------------------------------------------------------------
__device__ __forceinline__ uint32_t smem_u32_of(const void* p) {
    uint32_t a;
    asm("{ .reg .u64 t; cvta.to.shared.u64 t, %1; cvt.u32.u64 %0, t; }" : "=r"(a) : "l"(p));
    return a;
}

__device__ __forceinline__ void cp_async16(uint32_t saddr, const void* gptr) {
    asm volatile("cp.async.cg.shared.global [%0], [%1], 16;"
                 :: "r"(saddr), "l"(gptr) : "memory");
}

__device__ __forceinline__ void mma_bf16(float* c, const uint32_t* a, const uint32_t* b) {
    asm volatile(
        "mma.sync.aligned.m16n8k16.row.col.f32.bf16.bf16.f32 "
        "{%0,%1,%2,%3}, {%4,%5,%6,%7}, {%8,%9}, {%0,%1,%2,%3};"
        : "+f"(c[0]), "+f"(c[1]), "+f"(c[2]), "+f"(c[3])
        : "r"(a[0]), "r"(a[1]), "r"(a[2]), "r"(a[3]), "r"(b[0]), "r"(b[1]));
}

__device__ __forceinline__ void ldmatrix_x4(uint32_t& r0, uint32_t& r1,
                                            uint32_t& r2, uint32_t& r3, uint32_t addr) {
    asm volatile("ldmatrix.sync.aligned.m8n8.x4.shared.b16 {%0,%1,%2,%3}, [%4];"
                 : "=r"(r0), "=r"(r1), "=r"(r2), "=r"(r3) : "r"(addr));
}

__device__ __forceinline__ void packsplit2(float x, float y, uint32_t& hi, uint32_t& lo) {
    __nv_bfloat162 h = __floats2bfloat162_rn(x, y);
    float rx = x - __bfloat162float(h.x);
    float ry = y - __bfloat162float(h.y);
    __nv_bfloat162 l = __floats2bfloat162_rn(rx, ry);
    hi = *(uint32_t*)&h;
    lo = *(uint32_t*)&l;
}

// ---------------------------------------------------------------------------
// Split fp32 -> (hi, lo) bf16, elementwise
// ---------------------------------------------------------------------------
__global__ __launch_bounds__(256) void split_kernel(
    const float* __restrict__ in, __nv_bfloat16* __restrict__ hi,
    __nv_bfloat16* __restrict__ lo, int n4)
{
    int i = blockIdx.x * blockDim.x + threadIdx.x;
    if (i >= n4) return;
    float4 v = ((const float4*)in)[i];
    __nv_bfloat16 h0 = __float2bfloat16(v.x), h1 = __float2bfloat16(v.y);
    __nv_bfloat16 h2 = __float2bfloat16(v.z), h3 = __float2bfloat16(v.w);
    __nv_bfloat16 l0 = __float2bfloat16(v.x - __bfloat162float(h0));
    __nv_bfloat16 l1 = __float2bfloat16(v.y - __bfloat162float(h1));
    __nv_bfloat16 l2 = __float2bfloat16(v.z - __bfloat162float(h2));
    __nv_bfloat16 l3 = __float2bfloat16(v.w - __bfloat162float(h3));
    ((__nv_bfloat162*)hi)[i*2+0] = __nv_bfloat162(h0, h1);
    ((__nv_bfloat162*)hi)[i*2+1] = __nv_bfloat162(h2, h3);
    ((__nv_bfloat162*)lo)[i*2+0] = __nv_bfloat162(l0, l1);
    ((__nv_bfloat162*)lo)[i*2+1] = __nv_bfloat162(l2, l3);
}

// ---------------------------------------------------------------------------
// Transpose + split: W[K,N] fp32 -> Wt_hi/lo[N,K] bf16
// ---------------------------------------------------------------------------
__global__ __launch_bounds__(256) void transpose_split_kernel(
    const float* __restrict__ W, __nv_bfloat16* __restrict__ hi,
    __nv_bfloat16* __restrict__ lo, int K, int N)
{
    __shared__ float tile[32][33];
    const int tx = threadIdx.x, ty = threadIdx.y;
    const int n0 = blockIdx.x * 32, k0 = blockIdx.y * 32;
#pragma unroll
    for (int i = 0; i < 32; i += 8)
        tile[ty + i][tx] = W[(size_t)(k0 + ty + i) * N + n0 + tx];
    __syncthreads();
#pragma unroll
    for (int i = 0; i < 32; i += 8) {
        float v = tile[tx][ty + i];
        __nv_bfloat16 h = __float2bfloat16(v);
        __nv_bfloat16 l = __float2bfloat16(v - __bfloat162float(h));
        size_t o = (size_t)(n0 + ty + i) * K + (k0 + tx);
        hi[o] = h; lo[o] = l;
    }
}

// ---------------------------------------------------------------------------
// HMMA split-bf16 GEMM (Round-9 proven structure + ldmatrix fragment loads).
// Tile 128x128, 8 warps (2m x 4n), K-chunk 32, 2-stage cp.async pipeline.
// Smem row: 32 bf16 data + 8 pad = 40 bf16 = 80 B (ldmatrix conflict-free).
// ---------------------------------------------------------------------------
#define BKC      32
#define NCHUNK   (GK/BKC)            // 32
#define OPB      10240               // 128 rows * 80 B
#define STAGE_B  (4*OPB)             // 40960
#define GEMM_SMEM (2*STAGE_B)        // 81920

__global__ __launch_bounds__(256) void hmma_gemm_kernel(
    const __nv_bfloat16* __restrict__ Ahi, const __nv_bfloat16* __restrict__ Alo,
    const __nv_bfloat16* __restrict__ Bhi, const __nv_bfloat16* __restrict__ Blo,
    const float* __restrict__ bias, float* __restrict__ outp, int qkv_mode)
{
    extern __shared__ char smem[];
    const int tid  = threadIdx.x;
    const int lane = tid & 31;
    const int wid  = tid >> 5;
    const int warp_m = wid & 1;
    const int warp_n = wid >> 1;
    const int n0 = blockIdx.x << 7;
    const int m0 = blockIdx.y << 7;
    const int r4 = lane >> 2, c4 = lane & 3;

    // ldmatrix per-lane addressing: lane group lg selects matrix; rows at 80B stride
    const int lg   = lane >> 3;
    const int lrow8 = (lane & 7) + 8 * (lg & 1);     // row within 16-row tile
    const int lkoff = 16 * (lg >> 1);                // 0 or 16 bytes (k halves)

    const uint32_t sbase_all = smem_u32_of(smem);

    const __nv_bfloat16* gops[4] = {
        Ahi + (size_t)m0 * GK, Alo + (size_t)m0 * GK,
        Bhi + (size_t)n0 * GK, Blo + (size_t)n0 * GK };

    auto stage_load = [&](int c, int s) {
#pragma unroll
        for (int op = 0; op < 4; op++) {
            char* sd = smem + s * STAGE_B + op * OPB;
            const __nv_bfloat16* g = gops[op];
#pragma unroll
            for (int rep = 0; rep < 2; rep++) {
                int idx = tid + (rep << 8);
                int row = idx >> 2, q = idx & 3;
                uint32_t da = smem_u32_of(sd + row * 80 + q * 16);
                cp_async16(da, (const char*)(g + (size_t)row * GK + c * BKC) + q * 16);
            }
        }
    };

    float acc[4][4][4];
#pragma unroll
    for (int i = 0; i < 4; i++)
#pragma unroll
        for (int j = 0; j < 4; j++)
#pragma unroll
            for (int r = 0; r < 4; r++) acc[i][j][r] = 0.0f;

    stage_load(0, 0);
    asm volatile("cp.async.commit_group;" ::: "memory");

    for (int c = 0; c < NCHUNK; c++) {
        if (c + 1 < NCHUNK) {
            stage_load(c + 1, (c + 1) & 1);
            asm volatile("cp.async.commit_group;" ::: "memory");
            asm volatile("cp.async.wait_group 1;" ::: "memory");
        } else {
            asm volatile("cp.async.wait_group 0;" ::: "memory");
        }
        __syncthreads();

        const uint32_t st = sbase_all + (c & 1) * STAGE_B;
        // lane-resolved base addresses for ldmatrix (per operand)
        const uint32_t aAh = st           + (warp_m * 64 + lrow8) * 80 + lkoff;
        const uint32_t aAl = st +   OPB   + (warp_m * 64 + lrow8) * 80 + lkoff;
        const uint32_t aBh = st + 2*OPB   + (warp_n * 32 + lrow8) * 80 + lkoff;
        const uint32_t aBl = st + 3*OPB   + (warp_n * 32 + lrow8) * 80 + lkoff;

#pragma unroll
        for (int ks = 0; ks < 2; ks++) {
            const int ko = ks * 32;                  // 16 bf16 = 32 B per k-step
            uint32_t ah[4][4], al[4][4], bh[4][2], bl[4][2];
#pragma unroll
            for (int wm = 0; wm < 4; wm++) {
                ldmatrix_x4(ah[wm][0], ah[wm][1], ah[wm][2], ah[wm][3],
                            aAh + wm * (16 * 80) + ko);
                ldmatrix_x4(al[wm][0], al[wm][1], al[wm][2], al[wm][3],
                            aAl + wm * (16 * 80) + ko);
            }
#pragma unroll
            for (int wp = 0; wp < 2; wp++) {         // n-tile pairs (2 wn each)
                ldmatrix_x4(bh[2*wp][0], bh[2*wp+1][0], bh[2*wp][1], bh[2*wp+1][1],
                            aBh + wp * (16 * 80) + ko);
                ldmatrix_x4(bl[2*wp][0], bl[2*wp+1][0], bl[2*wp][1], bl[2*wp+1][1],
                            aBl + wp * (16 * 80) + ko);
            }
#pragma unroll
            for (int wm = 0; wm < 4; wm++)
#pragma unroll
                for (int wn = 0; wn < 4; wn++) {
                    mma_bf16(acc[wm][wn], ah[wm], bh[wn]);
                    mma_bf16(acc[wm][wn], ah[wm], bl[wn]);
                    mma_bf16(acc[wm][wn], al[wm], bh[wn]);
                }
        }
        __syncthreads();
    }

    // ---- Epilogue ----
#pragma unroll
    for (int wm = 0; wm < 4; wm++) {
#pragma unroll
        for (int wn = 0; wn < 4; wn++) {
            int col = n0 + warp_n * 32 + wn * 8 + (c4 << 1);
            float b0 = __ldg(bias + col), b1 = __ldg(bias + col + 1);
#pragma unroll
            for (int h8 = 0; h8 < 2; h8++) {
                int row = m0 + warp_m * 64 + wm * 16 + r4 + h8 * 8;
                float v0 = acc[wm][wn][h8*2+0] + b0;
                float v1 = acc[wm][wn][h8*2+1] + b1;
                if (qkv_mode) {
                    int three = col >> 10;
                    int h     = (col & 1023) >> 6;
                    int dcol  = col & 63;
                    if (three == 0) { v0 *= 0.125f; v1 *= 0.125f; }   // fold 1/sqrt(64)
                    __nv_bfloat16* dh = (three == 0) ? g_qhi : (three == 1) ? g_khi : g_vhi;
                    __nv_bfloat16* dl = (three == 0) ? g_qlo : (three == 1) ? g_klo : g_vlo;
                    uint32_t phv, plv;
                    packsplit2(v0, v1, phv, plv);
                    int b = row >> 11, t = row & 2047;
                    size_t o = ((size_t)(b*H_ + h)*T_ + t) * HD_ + dcol;
                    *(uint32_t*)(dh + o) = phv;
                    *(uint32_t*)(dl + o) = plv;
                } else {
                    float2 o2; o2.x = v0; o2.y = v1;
                    *(float2*)(outp + (size_t)row * D_ + col) = o2;
                }
            }
        }
    }
}

// ---------------------------------------------------------------------------
// HMMA flash attention (Round-10 passing version: fused split epilogue,
// reversed-qb scheduling).
// ---------------------------------------------------------------------------
#define KSTR 72          // padded smem row: 72 bf16 = 36 words (conflict-free)

__global__ __launch_bounds__(256) void attn_mma_kernel()
{
    __shared__ __nv_bfloat16 sK[2][64*KSTR];    // [hi/lo][token][dim]
    __shared__ __nv_bfloat16 sVt[2][64*KSTR];   // [hi/lo][dim][token]

    const int tid = threadIdx.x, lane = tid & 31, wid = tid >> 5;
    const int qb = gridDim.x - 1 - blockIdx.x;   // heavy blocks first
    const int bh = blockIdx.y;
    const int m0 = qb << 7;
    const int r4 = lane >> 2, c4 = lane & 3;
    const int rowblk = wid * 16 + r4;

    const size_t bho = (size_t)bh * T_ * HD_;
    const __nv_bfloat16* Kh = g_khi + bho;
    const __nv_bfloat16* Kl = g_klo + bho;
    const __nv_bfloat16* Vh = g_vhi + bho;
    const __nv_bfloat16* Vl = g_vlo + bho;

    // ---- Q fragments (pre-scaled), registers for whole sweep ----
    uint32_t qa[2][4][4];
    {
        const __nv_bfloat16* srcs[2] = { g_qhi + bho, g_qlo + bho };
#pragma unroll
        for (int hl = 0; hl < 2; hl++) {
            const __nv_bfloat16* S = srcs[hl];
            const size_t r0 = (size_t)(m0 + rowblk) * HD_;
            const size_t r8 = r0 + 8 * HD_;
#pragma unroll
            for (int ks = 0; ks < 4; ks++) {
                int col0 = ks * 16 + 2 * c4;
                qa[hl][ks][0] = *(const uint32_t*)(S + r0 + col0);
                qa[hl][ks][1] = *(const uint32_t*)(S + r8 + col0);
                qa[hl][ks][2] = *(const uint32_t*)(S + r0 + col0 + 8);
                qa[hl][ks][3] = *(const uint32_t*)(S + r8 + col0 + 8);
            }
        }
    }

    float m_i[2] = { -1e30f, -1e30f };
    float l_i[2] = { 0.0f, 0.0f };
    float o[8][4];
#pragma unroll
    for (int j = 0; j < 8; j++)
#pragma unroll
        for (int r = 0; r < 4; r++) o[j][r] = 0.0f;

    const int ktmax = 2 * qb + 1;
    for (int kt = 0; kt <= ktmax; kt++) {
        if (kt) __syncthreads();

#pragma unroll
        for (int hl = 0; hl < 2; hl++) {
            const __nv_bfloat16* src = hl ? Kl : Kh;
#pragma unroll
            for (int rep = 0; rep < 2; rep++) {
                int idx = tid + (rep << 8);
                int row = idx >> 3, ch = idx & 7;
                uint32_t da = smem_u32_of(&sK[hl][row * KSTR]) + ch * 16;
                cp_async16(da, (const char*)(src + (size_t)(kt*64 + row) * HD_) + ch * 16);
            }
        }
        asm volatile("cp.async.commit_group;" ::: "memory");

#pragma unroll
        for (int hl = 0; hl < 2; hl++) {
            const __nv_bfloat16* src = hl ? Vl : Vh;
#pragma unroll
            for (int rep = 0; rep < 4; rep++) {
                int idx = tid + (rep << 8);
                int t = idx >> 4, dg = (idx & 15) << 2;
                uint2 v = *(const uint2*)(src + (size_t)(kt*64 + t) * HD_ + dg);
                __nv_bfloat162 p0 = *(__nv_bfloat162*)&v.x;
                __nv_bfloat162 p1 = *(__nv_bfloat162*)&v.y;
                sVt[hl][(dg+0)*KSTR + t] = p0.x;
                sVt[hl][(dg+1)*KSTR + t] = p0.y;
                sVt[hl][(dg+2)*KSTR + t] = p1.x;
                sVt[hl][(dg+3)*KSTR + t] = p1.y;
            }
        }
        asm volatile("cp.async.wait_group 0;" ::: "memory");
        __syncthreads();

        const bool active = !(kt == ktmax && wid < 4);
        if (active) {
            float s[8][4];
#pragma unroll
            for (int j = 0; j < 8; j++)
#pragma unroll
                for (int r = 0; r < 4; r++) s[j][r] = 0.0f;

            const uint32_t* wKh = (const uint32_t*)sK[0];
            const uint32_t* wKl = (const uint32_t*)sK[1];
#pragma unroll
            for (int ks = 0; ks < 4; ks++) {
                const int w0 = ks * 8 + c4;
#pragma unroll
                for (int j = 0; j < 8; j++) {
                    int br = (j * 8 + r4) * 36;
                    uint32_t kb[2] = { wKh[br + w0], wKh[br + w0 + 4] };
                    uint32_t kl2[2] = { wKl[br + w0], wKl[br + w0 + 4] };
                    mma_bf16(s[j], qa[0][ks], kb);
                    mma_bf16(s[j], qa[0][ks], kl2);
                    mma_bf16(s[j], qa[1][ks], kb);
                }
            }

            if (kt >= 2 * qb) {
                int kbase = (kt - 2 * qb) << 6;
#pragma unroll
                for (int j = 0; j < 8; j++) {
                    int col = kbase + j * 8 + 2 * c4;
                    if (col     > rowblk)     s[j][0] = -1e30f;
                    if (col + 1 > rowblk)     s[j][1] = -1e30f;
                    if (col     > rowblk + 8) s[j][2] = -1e30f;
                    if (col + 1 > rowblk + 8) s[j][3] = -1e30f;
                }
            }

            float mx0 = -1e30f, mx1 = -1e30f;
#pragma unroll
            for (int j = 0; j < 8; j++) {
                mx0 = fmaxf(mx0, fmaxf(s[j][0], s[j][1]));
                mx1 = fmaxf(mx1, fmaxf(s[j][2], s[j][3]));
            }
            mx0 = fmaxf(mx0, __shfl_xor_sync(0xffffffffu, mx0, 1));
            mx0 = fmaxf(mx0, __shfl_xor_sync(0xffffffffu, mx0, 2));
            mx1 = fmaxf(mx1, __shfl_xor_sync(0xffffffffu, mx1, 1));
            mx1 = fmaxf(mx1, __shfl_xor_sync(0xffffffffu, mx1, 2));

            float mn0 = fmaxf(m_i[0], mx0), mn1 = fmaxf(m_i[1], mx1);
            float al0 = __expf(m_i[0] - mn0), al1 = __expf(m_i[1] - mn1);
            m_i[0] = mn0; m_i[1] = mn1;

            float rs0 = 0.0f, rs1 = 0.0f;
#pragma unroll
            for (int j = 0; j < 8; j++) {
                s[j][0] = __expf(s[j][0] - mn0);
                s[j][1] = __expf(s[j][1] - mn0);
                s[j][2] = __expf(s[j][2] - mn1);
                s[j][3] = __expf(s[j][3] - mn1);
                rs0 += s[j][0] + s[j][1];
                rs1 += s[j][2] + s[j][3];
            }
            rs0 += __shfl_xor_sync(0xffffffffu, rs0, 1);
            rs0 += __shfl_xor_sync(0xffffffffu, rs0, 2);
            rs1 += __shfl_xor_sync(0xffffffffu, rs1, 1);
            rs1 += __shfl_xor_sync(0xffffffffu, rs1, 2);
            l_i[0] = l_i[0] * al0 + rs0;
            l_i[1] = l_i[1] * al1 + rs1;

#pragma unroll
            for (int j = 0; j < 8; j++) {
                o[j][0] *= al0; o[j][1] *= al0;
                o[j][2] *= al1; o[j][3] *= al1;
            }

            const uint32_t* wVh = (const uint32_t*)sVt[0];
            const uint32_t* wVl = (const uint32_t*)sVt[1];
#pragma unroll
            for (int ks = 0; ks < 4; ks++) {
                uint32_t pah[4], pal[4];
                packsplit2(s[2*ks  ][0], s[2*ks  ][1], pah[0], pal[0]);
                packsplit2(s[2*ks  ][2], s[2*ks  ][3], pah[1], pal[1]);
                packsplit2(s[2*ks+1][0], s[2*ks+1][1], pah[2], pal[2]);
                packsplit2(s[2*ks+1][2], s[2*ks+1][3], pah[3], pal[3]);
                const int w0 = ks * 8 + c4;
#pragma unroll
                for (int j = 0; j < 8; j++) {
                    int br = (j * 8 + r4) * 36;
                    uint32_t vb[2] = { wVh[br + w0], wVh[br + w0 + 4] };
                    uint32_t vl2[2] = { wVl[br + w0], wVl[br + w0 + 4] };
                    mma_bf16(o[j], pah, vb);
                    mma_bf16(o[j], pah, vl2);
                    mma_bf16(o[j], pal, vb);
                }
            }
        }
    }

    // ---- normalize, split, write bf16 hi/lo att output [B,T,D] ----
    float inv0 = 1.0f / l_i[0], inv1 = 1.0f / l_i[1];
    const int b = bh >> 4, h = bh & 15;
    const int t0 = m0 + rowblk, t1 = t0 + 8;
#pragma unroll
    for (int j = 0; j < 8; j++) {
        int dim = h * 64 + j * 8 + 2 * c4;
        uint32_t h0, l0v, h1, l1v;
        packsplit2(o[j][0] * inv0, o[j][1] * inv0, h0, l0v);
        packsplit2(o[j][2] * inv1, o[j][3] * inv1, h1, l1v);
        size_t o0 = (size_t)(b*T_ + t0) * D_ + dim;
        size_t o1 = (size_t)(b*T_ + t1) * D_ + dim;
        *(uint32_t*)(g_atthi + o0) = h0;
        *(uint32_t*)(g_attlo + o0) = l0v;
        *(uint32_t*)(g_atthi + o1) = h1;
        *(uint32_t*)(g_attlo + o1) = l1v;
    }
}

// ---------------------------------------------------------------------------
extern "C" void kernel_launch(void* const* d_in, const int* in_sizes, int n_in,
                              void* d_out, int out_size)
{
    const float* x      = (const float*)d_in[0];
    const float* w_qkv  = (const float*)d_in[1];
    const float* b_qkv  = (const float*)d_in[2];
    const float* w_proj = (const float*)d_in[3];
    const float* b_proj = (const float*)d_in[4];
    float* out = (float*)d_out;

    __nv_bfloat16 *xhi, *xlo, *wqh, *wql, *wph, *wpl, *ahi, *alo;
    cudaGetSymbolAddress((void**)&xhi, g_xhi);
    cudaGetSymbolAddress((void**)&xlo, g_xlo);
    cudaGetSymbolAddress((void**)&wqh, g_wqkv_hi);
    cudaGetSymbolAddress((void**)&wql, g_wqkv_lo);
    cudaGetSymbolAddress((void**)&wph, g_wp_hi);
    cudaGetSymbolAddress((void**)&wpl, g_wp_lo);
    cudaGetSymbolAddress((void**)&ahi, g_atthi);
    cudaGetSymbolAddress((void**)&alo, g_attlo);

    cudaFuncSetAttribute(hmma_gemm_kernel,
                         cudaFuncAttributeMaxDynamicSharedMemorySize, GEMM_SMEM);

    // 1) split X, transpose+split weights
    split_kernel<<<(M_*D_/4 + 255)/256, 256>>>(x, xhi, xlo, M_*D_/4);
    transpose_split_kernel<<<dim3(NQKV/32, D_/32), dim3(32, 8)>>>(w_qkv, wqh, wql, D_, NQKV);
    transpose_split_kernel<<<dim3(D_/32,  D_/32), dim3(32, 8)>>>(w_proj, wph, wpl, D_, D_);

    // 2) QKV HMMA GEMM -> split-bf16 q/k/v (q pre-scaled)
    hmma_gemm_kernel<<<dim3(NQKV/128, M_/128), 256, GEMM_SMEM>>>(
        xhi, xlo, wqh, wql, b_qkv, nullptr, 1);

    // 3) HMMA flash attention -> split-bf16 att output (fused split epilogue)
    attn_mma_kernel<<<dim3(T_/128, B_*H_), 256>>>();

    // 4) proj HMMA GEMM -> out
    hmma_gemm_kernel<<<dim3(D_/128, M_/128), 256, GEMM_SMEM>>>(
        ahi, alo, wph, wpl, b_proj, out, 0);
}